// round 14
// baseline (speedup 1.0000x reference)
#include <cuda_runtime.h>
#include <cstdint>

// ============================================================================
// Problem sizes (fixed)
// ============================================================================
#define TOK   8192
#define KDIM  4096
#define ODIM  4096
#define NG    16
#define GRPSZ 256

#define X_ELEMS  ((size_t)TOK * KDIM)
#define W_ELEMS  ((size_t)ODIM * KDIM)
#define SZ_ELEMS ((size_t)ODIM * NG)
#define B_ELEMS  ((size_t)ODIM)

// Hybrid GEMM: CTA 256 rows x 64 cols, k-stage = 128, two DECOUPLED halves.
// Half 0 (warps 0-7):  rows 0-127 via IMMA,  own stages + own B copy.
// Half 1 (warps 8-15): rows 128-255 via dp4a, own stages + own B copy.
#define BMT 256
#define BMH 128
#define BN  64
#define BK  128
#define NSTAGE 4
#define KITERS (KDIM / BK)      // 32
#define H_A_BYTES (BMH * BK)    // 16384
#define H_B_BYTES (BN * BK)     // 8192
#define H_STAGE (H_A_BYTES + H_B_BYTES)   // 24576
#define H_TOTAL (NSTAGE * H_STAGE)        // 98304
#define DYN_SMEM (2 * H_TOTAL)            // 196608

#define MAGIC_I 0x4B400000
#define MAGICF  12582912.0f

// Scratch
__device__ __align__(1024) int8_t g_q[(size_t)TOK * KDIM];
__device__ __align__(1024) int8_t g_w8[(size_t)ODIM * KDIM];
__device__ float  g_srow[TOK];
__device__ float  g_zp[TOK];
__device__ float  g_Qg[(size_t)TOK * NG];
__device__ float  g_sz[(size_t)ODIM * NG];
__device__ float  g_C[ODIM];
__device__ int    g_swap;
__device__ int    g_wfmt;

// ============================================================================
// PTX helpers
// ============================================================================
__device__ __forceinline__ uint32_t smem_to_u32(const void* p) {
    uint32_t a;
    asm("{ .reg .u64 t; cvta.to.shared.u64 t, %1; cvt.u32.u64 %0, t; }"
        : "=r"(a) : "l"(p));
    return a;
}

__device__ __forceinline__ void cp_async16(uint32_t dst, const void* src) {
    asm volatile("cp.async.cg.shared.global [%0], [%1], 16;\n" :: "r"(dst), "l"(src));
}
__device__ __forceinline__ void cp_commit() {
    asm volatile("cp.async.commit_group;\n" ::: "memory");
}
#define CP_WAIT2() asm volatile("cp.async.wait_group 2;\n" ::: "memory")

#define BAR_HALF(id) \
    asm volatile("bar.sync %0, %1;" :: "r"(id), "r"(256) : "memory")

__device__ __forceinline__ void ldsm4(uint32_t* r, uint32_t addr) {
    asm volatile("ldmatrix.sync.aligned.m8n8.x4.shared.b16 {%0,%1,%2,%3}, [%4];\n"
        : "=r"(r[0]), "=r"(r[1]), "=r"(r[2]), "=r"(r[3]) : "r"(addr));
}

__device__ __forceinline__ void lds128(uint32_t* r, uint32_t addr) {
    asm volatile("ld.shared.v4.b32 {%0,%1,%2,%3}, [%4];\n"
        : "=r"(r[0]), "=r"(r[1]), "=r"(r[2]), "=r"(r[3]) : "r"(addr));
}

__device__ __forceinline__ void mma_s8(int* d, const uint32_t* a, uint32_t b0, uint32_t b1) {
    asm volatile(
        "mma.sync.aligned.m16n8k32.row.col.s32.s8.s8.s32 "
        "{%0,%1,%2,%3}, {%4,%5,%6,%7}, {%8,%9}, {%0,%1,%2,%3};\n"
        : "+r"(d[0]), "+r"(d[1]), "+r"(d[2]), "+r"(d[3])
        : "r"(a[0]), "r"(a[1]), "r"(a[2]), "r"(a[3]), "r"(b0), "r"(b1));
}

// ============================================================================
// Kernel 0a/0b/0c: weight format detect + repack, scales/zeros disambiguation
// ============================================================================
__global__ void wdetect_kernel(const int* __restrict__ w)
{
    int cnt = 0;
#pragma unroll
    for (int i = 0; i < 256; i++) {
        int v = w[i * 1001];
        cnt += (v >= -8 && v <= 7);
    }
    g_wfmt = (cnt > 200) ? 1 : 0;
}

__global__ void __launch_bounds__(256) wconv_kernel(const void* __restrict__ wraw)
{
    const size_t base = ((size_t)blockIdx.x * 256 + threadIdx.x) * 16;
    char4* dst = reinterpret_cast<char4*>(g_w8 + base);
    if (g_wfmt) {
        const int4* src = reinterpret_cast<const int4*>((const int*)wraw + base);
#pragma unroll
        for (int j = 0; j < 4; j++) {
            int4 v = src[j];
            char4 c;
            c.x = (signed char)v.x; c.y = (signed char)v.y;
            c.z = (signed char)v.z; c.w = (signed char)v.w;
            dst[j] = c;
        }
    } else {
        const int4 v = *reinterpret_cast<const int4*>((const int8_t*)wraw + base);
        *reinterpret_cast<int4*>(dst) = v;
    }
}

__global__ void pick_kernel(const float* __restrict__ p2, const float* __restrict__ p3)
{
    int integral2 = 0, integral3 = 0;
#pragma unroll
    for (int i = 0; i < 16; i++) {
        float a = p2[i * 97];
        float b = p3[i * 97];
        integral2 += (rintf(a) == a);
        integral3 += (rintf(b) == b);
    }
    g_swap = (integral2 > integral3) ? 1 : 0;
}

// ============================================================================
// Kernel 1: per-token asymmetric int8 quant (+ per-group sums).
// Per-element divide uses __fdividef (<=2ulp): a tie-flip changes one q by 1,
// perturbing the output by ~1e-6 relative — far below the 1e-3 threshold.
// ============================================================================
__global__ void __launch_bounds__(256) quant_kernel(const float* __restrict__ x)
{
    const int row = blockIdx.x;
    const int tid = threadIdx.x;
    const float4* xr = reinterpret_cast<const float4*>(x + (size_t)row * KDIM);

    __shared__ float smn[8], smx[8];
    __shared__ int sgrp[NG];
    if (tid < NG) sgrp[tid] = 0;

    float4 v[4];
    float mn = 0.f, mx = 0.f;
#pragma unroll
    for (int j = 0; j < 4; j++) {
        v[j] = xr[tid + 256 * j];
        mn = fminf(mn, fminf(fminf(v[j].x, v[j].y), fminf(v[j].z, v[j].w)));
        mx = fmaxf(mx, fmaxf(fmaxf(v[j].x, v[j].y), fmaxf(v[j].z, v[j].w)));
    }
#pragma unroll
    for (int off = 16; off; off >>= 1) {
        mn = fminf(mn, __shfl_xor_sync(0xFFFFFFFFu, mn, off));
        mx = fmaxf(mx, __shfl_xor_sync(0xFFFFFFFFu, mx, off));
    }
    if ((tid & 31) == 0) { smn[tid >> 5] = mn; smx[tid >> 5] = mx; }
    __syncthreads();
    mn = smn[0]; mx = smx[0];
#pragma unroll
    for (int i = 1; i < 8; i++) { mn = fminf(mn, smn[i]); mx = fmaxf(mx, smx[i]); }

    const float scale = fmaxf(__fdiv_rn(mx - mn, 255.0f), 1.1920928955078125e-07f);
    float zp = -128.0f - rintf(__fdiv_rn(mn, scale));
    zp = fminf(fmaxf(zp, -128.0f), 127.0f);
    const float rs = 1.0f / scale;

    char4* qrow = reinterpret_cast<char4*>(g_q + (size_t)row * KDIM);
#pragma unroll
    for (int j = 0; j < 4; j++) {
        int q0 = (int)(fminf(fmaxf(rintf(v[j].x * rs) + zp, -128.f), 127.f));
        int q1 = (int)(fminf(fmaxf(rintf(v[j].y * rs) + zp, -128.f), 127.f));
        int q2 = (int)(fminf(fmaxf(rintf(v[j].z * rs) + zp, -128.f), 127.f));
        int q3 = (int)(fminf(fmaxf(rintf(v[j].w * rs) + zp, -128.f), 127.f));
        char4 c4;
        c4.x = (signed char)q0; c4.y = (signed char)q1;
        c4.z = (signed char)q2; c4.w = (signed char)q3;
        qrow[tid + 256 * j] = c4;
        atomicAdd(&sgrp[(tid >> 6) + 4 * j], q0 + q1 + q2 + q3);
    }
    __syncthreads();
    if (tid < NG) g_Qg[(size_t)row * NG + tid] = (float)sgrp[tid];
    if (tid == 0) { g_srow[row] = scale; g_zp[row] = zp; }
}

// ============================================================================
// Kernel 2: weight-side precompute.
// ============================================================================
__global__ void __launch_bounds__(128) wprep_kernel(
    const float* __restrict__ p2, const float* __restrict__ p3)
{
    const float* scales = g_swap ? p3 : p2;
    const float* zeros  = g_swap ? p2 : p3;
    const int o = blockIdx.x;
    const int tid = threadIdx.x;
    __shared__ int wsum[NG];
    __shared__ float carr[NG];
    if (tid < NG) wsum[tid] = 0;
    __syncthreads();

    const int4* wr = reinterpret_cast<const int4*>(g_w8 + (size_t)o * KDIM);
    int4 a = wr[tid * 2], b = wr[tid * 2 + 1];
    int s = 0;
    s = __dp4a(a.x, 0x01010101, s); s = __dp4a(a.y, 0x01010101, s);
    s = __dp4a(a.z, 0x01010101, s); s = __dp4a(a.w, 0x01010101, s);
    s = __dp4a(b.x, 0x01010101, s); s = __dp4a(b.y, 0x01010101, s);
    s = __dp4a(b.z, 0x01010101, s); s = __dp4a(b.w, 0x01010101, s);
    atomicAdd(&wsum[tid >> 3], s);
    __syncthreads();

    if (tid < NG) {
        float sc = scales[o * NG + tid], z = zeros[o * NG + tid];
        g_sz[o * NG + tid] = sc * z;
        carr[tid] = sc * ((float)wsum[tid] - 256.0f * z);
    }
    __syncthreads();
    if (tid == 0) {
        float c = 0.f;
#pragma unroll
        for (int g = 0; g < NG; g++) c += carr[g];
        g_C[o] = c;
    }
}

// ============================================================================
// Kernel 3: hybrid IMMA + dp4a GEMM, two decoupled 256-thread pipelines.
// Each half: [A 16KB | B 8KB] x 4 stages, own cp.async groups, bar.sync id.
// ============================================================================
__device__ __forceinline__ void load_half_stage(
    uint32_t half_base, int ltid, const int8_t* __restrict__ arow0,
    const int8_t* __restrict__ brow0, int ks)
{
    const uint32_t sA = half_base + (uint32_t)(ks & (NSTAGE - 1)) * H_STAGE;
    const uint32_t sB = sA + H_A_BYTES;
    const int kb = ks * BK;
#pragma unroll
    for (int j = 0; j < 4; j++) {          // A: 128 rows x 8 chunks
        int idx = ltid + 256 * j;
        int rowi = idx >> 3, c = idx & 7;
        uint32_t off = (uint32_t)rowi * BK + ((uint32_t)(c ^ (rowi & 7)) << 4);
        cp_async16(sA + off, arow0 + (size_t)rowi * KDIM + kb + c * 16);
    }
#pragma unroll
    for (int j = 0; j < 2; j++) {          // B: 64 rows x 8 chunks
        int idx = ltid + 256 * j;
        int rowi = idx >> 3, c = idx & 7;
        uint32_t off = (uint32_t)rowi * BK + ((uint32_t)(c ^ (rowi & 7)) << 4);
        cp_async16(sB + off, brow0 + (size_t)rowi * KDIM + kb + c * 16);
    }
    cp_commit();
}

__global__ void __launch_bounds__(512, 1) gemm_kernel(
    const float* __restrict__ p2,
    const float* __restrict__ p3,
    const float* __restrict__ bias,
    float* __restrict__ out)
{
    const float* scales = g_swap ? p3 : p2;

    extern __shared__ char dynsm[];
    __shared__ float s_sm[NG * BN];
    __shared__ float sz_sm[NG * BN];
    __shared__ float Q_sm[BMT * NG];
    __shared__ float srow_sm[BMT], zp_sm[BMT], C_sm[BN], bias_sm[BN];

    const int tid = threadIdx.x;
    const int lane = tid & 31, wid = tid >> 5;
    const int n0 = blockIdx.x * BN, m0 = blockIdx.y * BMT;
    const uint32_t smem_base = smem_to_u32(dynsm);
    const int half = (tid >= 256);
    const int ltid = tid & 255;
    const uint32_t half_base = smem_base + (half ? H_TOTAL : 0u);
    const int8_t* arow0 = g_q + (size_t)(m0 + (half ? BMH : 0)) * KDIM;
    const int8_t* brow0 = g_w8 + (size_t)n0 * KDIM;

    for (int idx = tid; idx < NG * BN; idx += 512) {
        int g = idx >> 6, n = idx & (BN - 1);
        s_sm[idx]  = scales[(size_t)(n0 + n) * NG + g];
        sz_sm[idx] = g_sz[(size_t)(n0 + n) * NG + g];
    }
    for (int idx = tid; idx < BMT * NG; idx += 512)
        Q_sm[idx] = g_Qg[(size_t)m0 * NG + idx];
    if (tid < BMT) { srow_sm[tid] = g_srow[m0 + tid]; zp_sm[tid] = g_zp[m0 + tid]; }
    if (tid < BN)  { C_sm[tid] = g_C[n0 + tid]; bias_sm[tid] = bias[n0 + tid]; }

    load_half_stage(half_base, ltid, arow0, brow0, 0);
    load_half_stage(half_base, ltid, arow0, brow0, 1);
    load_half_stage(half_base, ltid, arow0, brow0, 2);
    __syncthreads();   // constants visible; after this, halves free-run

    if (!half) {
        // ================= IMMA half: rows m0 .. m0+127 =================
        const int wmm = wid >> 1, wmn = wid & 1;
        const int lr = lane & 7;
        const int lq = lane >> 3;
        const int qrow8 = (lq & 1) << 3;
        const int cq = lq >> 1;
        const int lg = lane >> 2;
        const int lw = lane & 3;

        int   iacc[2][4][4];
        float facc[2][4][4];
#pragma unroll
        for (int mt = 0; mt < 2; mt++)
#pragma unroll
            for (int nt = 0; nt < 4; nt++)
#pragma unroll
                for (int c = 0; c < 4; c++) { iacc[mt][nt][c] = MAGIC_I; facc[mt][nt][c] = 0.f; }

        for (int ks = 0; ks < KITERS; ks++) {
            CP_WAIT2();
            BAR_HALF(1);
            const uint32_t sA = half_base + (uint32_t)(ks & (NSTAGE - 1)) * H_STAGE;
            const uint32_t sB = sA + H_A_BYTES;
#pragma unroll
            for (int kk = 0; kk < 4; kk++) {
                uint32_t a[2][4], b[2][4];
#pragma unroll
                for (int mt = 0; mt < 2; mt++) {
                    int r = wmm * 32 + mt * 16 + qrow8 + lr;
                    uint32_t off = (uint32_t)r * BK
                                 + ((uint32_t)(((kk << 1) | cq) ^ (r & 7)) << 4);
                    ldsm4(a[mt], sA + off);
                }
#pragma unroll
                for (int p = 0; p < 2; p++) {
                    int r = wmn * 32 + p * 16 + qrow8 + lr;
                    uint32_t off = (uint32_t)r * BK
                                 + ((uint32_t)(((kk << 1) | cq) ^ (r & 7)) << 4);
                    ldsm4(b[p], sB + off);
                }
#pragma unroll
                for (int mt = 0; mt < 2; mt++)
#pragma unroll
                    for (int nt = 0; nt < 4; nt++)
                        mma_s8(iacc[mt][nt], a[mt],
                               b[nt >> 1][nt & 1], b[nt >> 1][2 + (nt & 1)]);
            }
            if (ks & 1) {
                const int g = ks >> 1;
                const int nb = wmn * 32 + 2 * lw;
#pragma unroll
                for (int nt = 0; nt < 4; nt++) {
                    float se = s_sm[g * BN + nb + nt * 8];
                    float so = s_sm[g * BN + nb + nt * 8 + 1];
#pragma unroll
                    for (int mt = 0; mt < 2; mt++) {
                        facc[mt][nt][0] = fmaf(__int_as_float(iacc[mt][nt][0]) - MAGICF, se, facc[mt][nt][0]);
                        facc[mt][nt][1] = fmaf(__int_as_float(iacc[mt][nt][1]) - MAGICF, so, facc[mt][nt][1]);
                        facc[mt][nt][2] = fmaf(__int_as_float(iacc[mt][nt][2]) - MAGICF, se, facc[mt][nt][2]);
                        facc[mt][nt][3] = fmaf(__int_as_float(iacc[mt][nt][3]) - MAGICF, so, facc[mt][nt][3]);
                        iacc[mt][nt][0] = MAGIC_I; iacc[mt][nt][1] = MAGIC_I;
                        iacc[mt][nt][2] = MAGIC_I; iacc[mt][nt][3] = MAGIC_I;
                    }
                }
            }
            if (ks + 3 < KITERS) load_half_stage(half_base, ltid, arow0, brow0, ks + 3);
            else                 cp_commit();
        }

        // epilogue (mma half)
#pragma unroll
        for (int mt = 0; mt < 2; mt++) {
            const int mlo = wmm * 32 + mt * 16 + lg;
            const int mhi = mlo + 8;
            float Ql[NG], Qh[NG];
#pragma unroll
            for (int g = 0; g < NG; g++) { Ql[g] = Q_sm[mlo * NG + g]; Qh[g] = Q_sm[mhi * NG + g]; }
            const float sl = srow_sm[mlo], sh = srow_sm[mhi];
            const float zl = zp_sm[mlo],  zh = zp_sm[mhi];
            float* orow_lo = out + (size_t)(m0 + mlo) * ODIM + n0;
            float* orow_hi = out + (size_t)(m0 + mhi) * ODIM + n0;
#pragma unroll
            for (int nt = 0; nt < 4; nt++) {
                const int ne = wmn * 32 + nt * 8 + 2 * lw;
                float dle = 0.f, dlo = 0.f, dhe = 0.f, dho = 0.f;
#pragma unroll
                for (int g = 0; g < NG; g++) {
                    float sze = sz_sm[g * BN + ne], szo = sz_sm[g * BN + ne + 1];
                    dle = fmaf(Ql[g], sze, dle);
                    dlo = fmaf(Ql[g], szo, dlo);
                    dhe = fmaf(Qh[g], sze, dhe);
                    dho = fmaf(Qh[g], szo, dho);
                }
                float2 v0, v1;
                v0.x = fmaf(sl, facc[mt][nt][0] - dle - zl * C_sm[ne],     bias_sm[ne]);
                v0.y = fmaf(sl, facc[mt][nt][1] - dlo - zl * C_sm[ne + 1], bias_sm[ne + 1]);
                v1.x = fmaf(sh, facc[mt][nt][2] - dhe - zh * C_sm[ne],     bias_sm[ne]);
                v1.y = fmaf(sh, facc[mt][nt][3] - dho - zh * C_sm[ne + 1], bias_sm[ne + 1]);
                *reinterpret_cast<float2*>(orow_lo + ne) = v0;
                *reinterpret_cast<float2*>(orow_hi + ne) = v1;
            }
        }
    } else {
        // ================= dp4a half: rows m0+128 .. m0+255 =================
        const int dwid = wid - 8;
        const int wdm = dwid >> 1, wdn = dwid & 1;
        const int lr2 = lane >> 3;
        const int lc3 = lane & 7;
        const int rloc = wdm * 32 + lr2;           // row in dp tile (+4a)
        const int cbase = wdn * 32 + lc3;          // col base (+8b)

        int   iacc[8][4];
        float facc[8][4];
#pragma unroll
        for (int a = 0; a < 8; a++)
#pragma unroll
            for (int b = 0; b < 4; b++) { iacc[a][b] = 0; facc[a][b] = 0.f; }

        for (int ks = 0; ks < KITERS; ks++) {
            CP_WAIT2();
            BAR_HALF(2);
            const uint32_t sD = half_base + (uint32_t)(ks & (NSTAGE - 1)) * H_STAGE;
            const uint32_t sB = sD + H_A_BYTES;
#pragma unroll
            for (int ch = 0; ch < 8; ch++) {
                uint32_t bv[4][4];
#pragma unroll
                for (int b = 0; b < 4; b++) {
                    const int col = cbase + 8 * b;
                    lds128(bv[b], sB + (uint32_t)col * BK
                                 + ((uint32_t)(ch ^ (col & 7)) << 4));
                }
#pragma unroll
                for (int a = 0; a < 8; a++) {
                    const int r = rloc + 4 * a;
                    uint32_t av[4];
                    lds128(av, sD + (uint32_t)r * BK
                              + ((uint32_t)(ch ^ (r & 7)) << 4));
#pragma unroll
                    for (int b = 0; b < 4; b++) {
                        iacc[a][b] = __dp4a((int)av[0], (int)bv[b][0], iacc[a][b]);
                        iacc[a][b] = __dp4a((int)av[1], (int)bv[b][1], iacc[a][b]);
                        iacc[a][b] = __dp4a((int)av[2], (int)bv[b][2], iacc[a][b]);
                        iacc[a][b] = __dp4a((int)av[3], (int)bv[b][3], iacc[a][b]);
                    }
                }
            }
            if (ks & 1) {
                const int g = ks >> 1;
#pragma unroll
                for (int b = 0; b < 4; b++) {
                    float sb = s_sm[g * BN + cbase + 8 * b];
#pragma unroll
                    for (int a = 0; a < 8; a++) {
                        facc[a][b] = fmaf(
                            __int_as_float(iacc[a][b] + MAGIC_I) - MAGICF, sb, facc[a][b]);
                        iacc[a][b] = 0;
                    }
                }
            }
            if (ks + 3 < KITERS) load_half_stage(half_base, ltid, arow0, brow0, ks + 3);
            else                 cp_commit();
        }

        // epilogue (dp4a half)
#pragma unroll
        for (int a = 0; a < 8; a++) {
            const int m = BMH + rloc + 4 * a;
            float Qv[NG];
#pragma unroll
            for (int g = 0; g < NG; g++) Qv[g] = Q_sm[m * NG + g];
            const float sl = srow_sm[m], zl = zp_sm[m];
            float* orow = out + (size_t)(m0 + m) * ODIM + n0;
#pragma unroll
            for (int b = 0; b < 4; b++) {
                const int ne = cbase + 8 * b;
                float d = 0.f;
#pragma unroll
                for (int g = 0; g < NG; g++)
                    d = fmaf(Qv[g], sz_sm[g * BN + ne], d);
                orow[ne] = fmaf(sl, facc[a][b] - d - zl * C_sm[ne], bias_sm[ne]);
            }
        }
    }
}

// ============================================================================
// Host launch
// ============================================================================
extern "C" void kernel_launch(void* const* d_in, const int* in_sizes, int n_in,
                              void* d_out, int out_size)
{
    const float* x    = nullptr;
    const void*  wraw = nullptr;
    const float* bias = nullptr;
    const float* amb[2] = {nullptr, nullptr};
    int na = 0;

    for (int i = 0; i < n_in; i++) {
        const size_t sz = (size_t)in_sizes[i];
        if (sz == X_ELEMS)       x = (const float*)d_in[i];
        else if (sz == W_ELEMS)  wraw = d_in[i];
        else if (sz == B_ELEMS)  bias = (const float*)d_in[i];
        else if (sz == SZ_ELEMS && na < 2) amb[na++] = (const float*)d_in[i];
    }
    if (!x)    x    = (const float*)d_in[0];
    if (!wraw) wraw = d_in[1];
    if (na < 2) { amb[0] = (const float*)d_in[2]; amb[1] = (const float*)d_in[3]; }
    if (!bias) bias = (const float*)d_in[4];

    float* out = (float*)d_out;

    wdetect_kernel<<<1, 1>>>((const int*)wraw);
    pick_kernel<<<1, 1>>>(amb[0], amb[1]);
    wconv_kernel<<<W_ELEMS / (256 * 16), 256>>>(wraw);
    quant_kernel<<<TOK, 256>>>(x);
    wprep_kernel<<<ODIM, 128>>>(amb[0], amb[1]);

    cudaFuncSetAttribute(gemm_kernel, cudaFuncAttributeMaxDynamicSharedMemorySize,
                         DYN_SMEM);
    dim3 grid(ODIM / BN, TOK / BMT);   // (64, 32)
    gemm_kernel<<<grid, 512, DYN_SMEM>>>(amb[0], amb[1], bias, out);
}

// round 15
// speedup vs baseline: 1.0449x; 1.0449x over previous
#include <cuda_runtime.h>
#include <cstdint>

// ============================================================================
// Problem sizes (fixed)
// ============================================================================
#define TOK   8192
#define KDIM  4096
#define ODIM  4096
#define NG    16
#define GRPSZ 256

#define X_ELEMS  ((size_t)TOK * KDIM)
#define W_ELEMS  ((size_t)ODIM * KDIM)
#define SZ_ELEMS ((size_t)ODIM * NG)
#define B_ELEMS  ((size_t)ODIM)

// Hybrid GEMM tiling: CTA 256 rows x 64 cols, k-stage = 128.
// Warps 0-7: rows 0-127 via IMMA (also issue ALL cp.async loads).
// Warps 8-15: rows 128-255 via dp4a (issue only compute).
#define BMT 256
#define BMH 128
#define BN  64
#define BK  128
#define NSTAGE 4
#define KITERS (KDIM / BK)    // 32
#define A_BYTES (BMH * BK)    // 16384 (A_mma)
#define D_BYTES (BMH * BK)    // 16384 (A_dp)
#define B_BYTES (BN * BK)     // 8192
#define STAGE_BYTES (A_BYTES + D_BYTES + B_BYTES)  // 40960
#define DYN_SMEM (NSTAGE * STAGE_BYTES)            // 163840

#define MAGIC_I 0x4B400000
#define MAGICF  12582912.0f

#define WCONV_BLOCKS 4096     // fused prep: blocks [0, 4096) = wconv

// Scratch
__device__ __align__(1024) int8_t g_q[(size_t)TOK * KDIM];
__device__ __align__(1024) int8_t g_w8[(size_t)ODIM * KDIM];
__device__ float  g_srow[TOK];
__device__ float  g_zp[TOK];
__device__ float  g_Qg[(size_t)TOK * NG];
__device__ float  g_sz[(size_t)ODIM * NG];
__device__ float  g_C[ODIM];
__device__ int    g_swap;
__device__ int    g_wfmt;

// ============================================================================
// PTX helpers
// ============================================================================
__device__ __forceinline__ uint32_t smem_to_u32(const void* p) {
    uint32_t a;
    asm("{ .reg .u64 t; cvta.to.shared.u64 t, %1; cvt.u32.u64 %0, t; }"
        : "=r"(a) : "l"(p));
    return a;
}

__device__ __forceinline__ void cp_async16(uint32_t dst, const void* src) {
    asm volatile("cp.async.cg.shared.global [%0], [%1], 16;\n" :: "r"(dst), "l"(src));
}
__device__ __forceinline__ void cp_commit() {
    asm volatile("cp.async.commit_group;\n" ::: "memory");
}
#define CP_WAIT2() asm volatile("cp.async.wait_group 2;\n" ::: "memory")

__device__ __forceinline__ void ldsm4(uint32_t* r, uint32_t addr) {
    asm volatile("ldmatrix.sync.aligned.m8n8.x4.shared.b16 {%0,%1,%2,%3}, [%4];\n"
        : "=r"(r[0]), "=r"(r[1]), "=r"(r[2]), "=r"(r[3]) : "r"(addr));
}

__device__ __forceinline__ void lds128(uint32_t* r, uint32_t addr) {
    asm volatile("ld.shared.v4.b32 {%0,%1,%2,%3}, [%4];\n"
        : "=r"(r[0]), "=r"(r[1]), "=r"(r[2]), "=r"(r[3]) : "r"(addr));
}

__device__ __forceinline__ void mma_s8(int* d, const uint32_t* a, uint32_t b0, uint32_t b1) {
    asm volatile(
        "mma.sync.aligned.m16n8k32.row.col.s32.s8.s8.s32 "
        "{%0,%1,%2,%3}, {%4,%5,%6,%7}, {%8,%9}, {%0,%1,%2,%3};\n"
        : "+r"(d[0]), "+r"(d[1]), "+r"(d[2]), "+r"(d[3])
        : "r"(a[0]), "r"(a[1]), "r"(a[2]), "r"(a[3]), "r"(b0), "r"(b1));
}

// ============================================================================
// Kernel 0: weight-format detect + scales/zeros disambiguation (one launch).
// ============================================================================
__global__ void detpick_kernel(const int* __restrict__ w,
                               const float* __restrict__ p2,
                               const float* __restrict__ p3)
{
    int cnt = 0;
#pragma unroll
    for (int i = 0; i < 256; i++) {
        int v = w[i * 1001];
        cnt += (v >= -8 && v <= 7);
    }
    g_wfmt = (cnt > 200) ? 1 : 0;

    int integral2 = 0, integral3 = 0;
#pragma unroll
    for (int i = 0; i < 16; i++) {
        float a = p2[i * 97];
        float b = p3[i * 97];
        integral2 += (rintf(a) == a);
        integral3 += (rintf(b) == b);
    }
    g_swap = (integral2 > integral3) ? 1 : 0;
}

// ============================================================================
// Kernel 1 (fused): blocks [0,4096) repack weights; blocks [4096,12288) do
// per-token quant. Both are HBM-streaming; fusing overlaps their traffic.
// ============================================================================
__global__ void __launch_bounds__(256) prep_kernel(
    const void* __restrict__ wraw, const float* __restrict__ x)
{
    const int tid = threadIdx.x;

    if (blockIdx.x < WCONV_BLOCKS) {
        // ---- weight repack: int32-per-value or packed int8 -> g_w8 ----
        const size_t base = ((size_t)blockIdx.x * 256 + tid) * 16;
        char4* dst = reinterpret_cast<char4*>(g_w8 + base);
        if (g_wfmt) {
            const int4* src = reinterpret_cast<const int4*>((const int*)wraw + base);
#pragma unroll
            for (int j = 0; j < 4; j++) {
                int4 v = src[j];
                char4 c;
                c.x = (signed char)v.x; c.y = (signed char)v.y;
                c.z = (signed char)v.z; c.w = (signed char)v.w;
                dst[j] = c;
            }
        } else {
            const int4 v = *reinterpret_cast<const int4*>((const int8_t*)wraw + base);
            *reinterpret_cast<int4*>(dst) = v;
        }
        return;
    }

    // ---- per-token asymmetric int8 quant (+ per-group sums) ----
    const int row = blockIdx.x - WCONV_BLOCKS;
    const int lane = tid & 31, wid = tid >> 5;
    const float4* xr = reinterpret_cast<const float4*>(x + (size_t)row * KDIM);

    __shared__ float smn[8], smx[8];
    __shared__ int sgrp[NG];
    if (tid < NG) sgrp[tid] = 0;

    float4 v[4];
    float mn = 0.f, mx = 0.f;
#pragma unroll
    for (int j = 0; j < 4; j++) {
        v[j] = xr[tid + 256 * j];
        mn = fminf(mn, fminf(fminf(v[j].x, v[j].y), fminf(v[j].z, v[j].w)));
        mx = fmaxf(mx, fmaxf(fmaxf(v[j].x, v[j].y), fmaxf(v[j].z, v[j].w)));
    }
#pragma unroll
    for (int off = 16; off; off >>= 1) {
        mn = fminf(mn, __shfl_xor_sync(0xFFFFFFFFu, mn, off));
        mx = fmaxf(mx, __shfl_xor_sync(0xFFFFFFFFu, mx, off));
    }
    if (lane == 0) { smn[wid] = mn; smx[wid] = mx; }
    __syncthreads();
    mn = smn[0]; mx = smx[0];
#pragma unroll
    for (int i = 1; i < 8; i++) { mn = fminf(mn, smn[i]); mx = fmaxf(mx, smx[i]); }

    const float scale = fmaxf(__fdiv_rn(mx - mn, 255.0f), 1.1920928955078125e-07f);
    float zp = -128.0f - rintf(__fdiv_rn(mn, scale));
    zp = fminf(fmaxf(zp, -128.0f), 127.0f);
    const float rs = 1.0f / scale;

    char4* qrow = reinterpret_cast<char4*>(g_q + (size_t)row * KDIM);
#pragma unroll
    for (int j = 0; j < 4; j++) {
        int q0 = (int)(fminf(fmaxf(rintf(v[j].x * rs) + zp, -128.f), 127.f));
        int q1 = (int)(fminf(fmaxf(rintf(v[j].y * rs) + zp, -128.f), 127.f));
        int q2 = (int)(fminf(fmaxf(rintf(v[j].z * rs) + zp, -128.f), 127.f));
        int q3 = (int)(fminf(fmaxf(rintf(v[j].w * rs) + zp, -128.f), 127.f));
        char4 c4;
        c4.x = (signed char)q0; c4.y = (signed char)q1;
        c4.z = (signed char)q2; c4.w = (signed char)q3;
        qrow[tid + 256 * j] = c4;
        // group id (tid>>6)+4j is warp-uniform: warp-reduce, single atomic
        int s = q0 + q1 + q2 + q3;
#pragma unroll
        for (int off = 16; off; off >>= 1)
            s += __shfl_xor_sync(0xFFFFFFFFu, s, off);
        if (lane == 0) atomicAdd(&sgrp[(wid >> 1) + 4 * j], s);
    }
    __syncthreads();
    if (tid < NG) g_Qg[(size_t)row * NG + tid] = (float)sgrp[tid];
    if (tid == 0) { g_srow[row] = scale; g_zp[row] = zp; }
}

// ============================================================================
// Kernel 2: weight-side precompute.
// ============================================================================
__global__ void __launch_bounds__(128) wprep_kernel(
    const float* __restrict__ p2, const float* __restrict__ p3)
{
    const float* scales = g_swap ? p3 : p2;
    const float* zeros  = g_swap ? p2 : p3;
    const int o = blockIdx.x;
    const int tid = threadIdx.x;
    __shared__ int wsum[NG];
    __shared__ float carr[NG];
    if (tid < NG) wsum[tid] = 0;
    __syncthreads();

    const int4* wr = reinterpret_cast<const int4*>(g_w8 + (size_t)o * KDIM);
    int4 a = wr[tid * 2], b = wr[tid * 2 + 1];
    int s = 0;
    s = __dp4a(a.x, 0x01010101, s); s = __dp4a(a.y, 0x01010101, s);
    s = __dp4a(a.z, 0x01010101, s); s = __dp4a(a.w, 0x01010101, s);
    s = __dp4a(b.x, 0x01010101, s); s = __dp4a(b.y, 0x01010101, s);
    s = __dp4a(b.z, 0x01010101, s); s = __dp4a(b.w, 0x01010101, s);
    atomicAdd(&wsum[tid >> 3], s);
    __syncthreads();

    if (tid < NG) {
        float sc = scales[o * NG + tid], z = zeros[o * NG + tid];
        g_sz[o * NG + tid] = sc * z;
        carr[tid] = sc * ((float)wsum[tid] - 256.0f * z);
    }
    __syncthreads();
    if (tid == 0) {
        float c = 0.f;
#pragma unroll
        for (int g = 0; g < NG; g++) c += carr[g];
        g_C[o] = c;
    }
}

// ============================================================================
// Kernel 3: hybrid IMMA + dp4a GEMM. CTA 256x64, 512 threads.
// Stage: [A_mma 16KB | A_dp 16KB | B 8KB], xor-swizzled 128B rows.
// ALL loads issued by threads 0-255 (the IMMA warps, which have issue slack);
// dp4a warps issue only compute — keeps the rt2 fma pipe paced.
// ============================================================================
__device__ __forceinline__ void load_stage(
    uint32_t smem_base, int tid, int m0, int n0, int ks)
{
    // called only by tid < 256
    const uint32_t sA = smem_base + (uint32_t)(ks & (NSTAGE - 1)) * STAGE_BYTES;
    const uint32_t sD = sA + A_BYTES;
    const uint32_t sB = sD + D_BYTES;
    const int kb = ks * BK;
#pragma unroll
    for (int j = 0; j < 4; j++) {           // A_mma + A_dp: 128 rows x 8 chunks
        int idx = tid + 256 * j;
        int rowi = idx >> 3, c = idx & 7;
        uint32_t off = (uint32_t)rowi * BK + ((uint32_t)(c ^ (rowi & 7)) << 4);
        cp_async16(sA + off, g_q + (size_t)(m0 + rowi) * KDIM + kb + c * 16);
        cp_async16(sD + off, g_q + (size_t)(m0 + BMH + rowi) * KDIM + kb + c * 16);
    }
#pragma unroll
    for (int j = 0; j < 2; j++) {           // B: 64 rows x 8 chunks
        int idx = tid + 256 * j;
        int rowi = idx >> 3, c = idx & 7;
        uint32_t off = (uint32_t)rowi * BK + ((uint32_t)(c ^ (rowi & 7)) << 4);
        cp_async16(sB + off, g_w8 + (size_t)(n0 + rowi) * KDIM + kb + c * 16);
    }
    cp_commit();
}

__global__ void __launch_bounds__(512, 1) gemm_kernel(
    const float* __restrict__ p2,
    const float* __restrict__ p3,
    const float* __restrict__ bias,
    float* __restrict__ out)
{
    const float* scales = g_swap ? p3 : p2;

    extern __shared__ char dynsm[];
    __shared__ float s_sm[NG * BN];
    __shared__ float sz_sm[NG * BN];
    __shared__ float Q_sm[BMT * NG];
    __shared__ float srow_sm[BMT], zp_sm[BMT], C_sm[BN], bias_sm[BN];

    const int tid = threadIdx.x;
    const int lane = tid & 31, wid = tid >> 5;
    const int n0 = blockIdx.x * BN, m0 = blockIdx.y * BMT;
    const uint32_t smem_base = smem_to_u32(dynsm);

    for (int idx = tid; idx < NG * BN; idx += 512) {
        int g = idx >> 6, n = idx & (BN - 1);
        s_sm[idx]  = scales[(size_t)(n0 + n) * NG + g];
        sz_sm[idx] = g_sz[(size_t)(n0 + n) * NG + g];
    }
    for (int idx = tid; idx < BMT * NG; idx += 512)
        Q_sm[idx] = g_Qg[(size_t)m0 * NG + idx];
    if (tid < BMT) { srow_sm[tid] = g_srow[m0 + tid]; zp_sm[tid] = g_zp[m0 + tid]; }
    if (tid < BN)  { C_sm[tid] = g_C[n0 + tid]; bias_sm[tid] = bias[n0 + tid]; }

    if (tid < 256) {
        load_stage(smem_base, tid, m0, n0, 0);
        load_stage(smem_base, tid, m0, n0, 1);
        load_stage(smem_base, tid, m0, n0, 2);
    }

    if (wid < 8) {
        // ================= IMMA half: rows m0 .. m0+127 =================
        const int wmm = wid >> 1, wmn = wid & 1;
        const int lr = lane & 7;
        const int lq = lane >> 3;
        const int qrow8 = (lq & 1) << 3;
        const int cq = lq >> 1;
        const int lg = lane >> 2;
        const int lw = lane & 3;

        int   iacc[2][4][4];
        float facc[2][4][4];
#pragma unroll
        for (int mt = 0; mt < 2; mt++)
#pragma unroll
            for (int nt = 0; nt < 4; nt++)
#pragma unroll
                for (int c = 0; c < 4; c++) { iacc[mt][nt][c] = MAGIC_I; facc[mt][nt][c] = 0.f; }

        for (int ks = 0; ks < KITERS; ks++) {
            CP_WAIT2();
            __syncthreads();
            const uint32_t sA = smem_base + (uint32_t)(ks & (NSTAGE - 1)) * STAGE_BYTES;
            const uint32_t sB = sA + A_BYTES + D_BYTES;
#pragma unroll
            for (int kk = 0; kk < 4; kk++) {
                uint32_t a[2][4], b[2][4];
#pragma unroll
                for (int mt = 0; mt < 2; mt++) {
                    int r = wmm * 32 + mt * 16 + qrow8 + lr;
                    uint32_t off = (uint32_t)r * BK
                                 + ((uint32_t)(((kk << 1) | cq) ^ (r & 7)) << 4);
                    ldsm4(a[mt], sA + off);
                }
#pragma unroll
                for (int p = 0; p < 2; p++) {
                    int r = wmn * 32 + p * 16 + qrow8 + lr;
                    uint32_t off = (uint32_t)r * BK
                                 + ((uint32_t)(((kk << 1) | cq) ^ (r & 7)) << 4);
                    ldsm4(b[p], sB + off);
                }
#pragma unroll
                for (int mt = 0; mt < 2; mt++)
#pragma unroll
                    for (int nt = 0; nt < 4; nt++)
                        mma_s8(iacc[mt][nt], a[mt],
                               b[nt >> 1][nt & 1], b[nt >> 1][2 + (nt & 1)]);
            }
            if (ks & 1) {
                const int g = ks >> 1;
                const int nb = wmn * 32 + 2 * lw;
#pragma unroll
                for (int nt = 0; nt < 4; nt++) {
                    float se = s_sm[g * BN + nb + nt * 8];
                    float so = s_sm[g * BN + nb + nt * 8 + 1];
#pragma unroll
                    for (int mt = 0; mt < 2; mt++) {
                        facc[mt][nt][0] = fmaf(__int_as_float(iacc[mt][nt][0]) - MAGICF, se, facc[mt][nt][0]);
                        facc[mt][nt][1] = fmaf(__int_as_float(iacc[mt][nt][1]) - MAGICF, so, facc[mt][nt][1]);
                        facc[mt][nt][2] = fmaf(__int_as_float(iacc[mt][nt][2]) - MAGICF, se, facc[mt][nt][2]);
                        facc[mt][nt][3] = fmaf(__int_as_float(iacc[mt][nt][3]) - MAGICF, so, facc[mt][nt][3]);
                        iacc[mt][nt][0] = MAGIC_I; iacc[mt][nt][1] = MAGIC_I;
                        iacc[mt][nt][2] = MAGIC_I; iacc[mt][nt][3] = MAGIC_I;
                    }
                }
            }
            if (ks + 3 < KITERS) load_stage(smem_base, tid, m0, n0, ks + 3);
            else                 cp_commit();
        }

        // epilogue (mma half)
#pragma unroll
        for (int mt = 0; mt < 2; mt++) {
            const int mlo = wmm * 32 + mt * 16 + lg;
            const int mhi = mlo + 8;
            float Ql[NG], Qh[NG];
#pragma unroll
            for (int g = 0; g < NG; g++) { Ql[g] = Q_sm[mlo * NG + g]; Qh[g] = Q_sm[mhi * NG + g]; }
            const float sl = srow_sm[mlo], sh = srow_sm[mhi];
            const float zl = zp_sm[mlo],  zh = zp_sm[mhi];
            float* orow_lo = out + (size_t)(m0 + mlo) * ODIM + n0;
            float* orow_hi = out + (size_t)(m0 + mhi) * ODIM + n0;
#pragma unroll
            for (int nt = 0; nt < 4; nt++) {
                const int ne = wmn * 32 + nt * 8 + 2 * lw;
                float dle = 0.f, dlo = 0.f, dhe = 0.f, dho = 0.f;
#pragma unroll
                for (int g = 0; g < NG; g++) {
                    float sze = sz_sm[g * BN + ne], szo = sz_sm[g * BN + ne + 1];
                    dle = fmaf(Ql[g], sze, dle);
                    dlo = fmaf(Ql[g], szo, dlo);
                    dhe = fmaf(Qh[g], sze, dhe);
                    dho = fmaf(Qh[g], szo, dho);
                }
                float2 v0, v1;
                v0.x = fmaf(sl, facc[mt][nt][0] - dle - zl * C_sm[ne],     bias_sm[ne]);
                v0.y = fmaf(sl, facc[mt][nt][1] - dlo - zl * C_sm[ne + 1], bias_sm[ne + 1]);
                v1.x = fmaf(sh, facc[mt][nt][2] - dhe - zh * C_sm[ne],     bias_sm[ne]);
                v1.y = fmaf(sh, facc[mt][nt][3] - dho - zh * C_sm[ne + 1], bias_sm[ne + 1]);
                *reinterpret_cast<float2*>(orow_lo + ne) = v0;
                *reinterpret_cast<float2*>(orow_hi + ne) = v1;
            }
        }
    } else {
        // ================= dp4a half: rows m0+128 .. m0+255 =================
        const int dwid = wid - 8;
        const int wdm = dwid >> 1, wdn = dwid & 1;
        const int lr2 = lane >> 3;
        const int lc3 = lane & 7;
        const int rloc = wdm * 32 + lr2;           // row in dp tile (+4a)
        const int cbase = wdn * 32 + lc3;          // col base (+8b)

        int   iacc[8][4];
        float facc[8][4];
#pragma unroll
        for (int a = 0; a < 8; a++)
#pragma unroll
            for (int b = 0; b < 4; b++) { iacc[a][b] = 0; facc[a][b] = 0.f; }

        for (int ks = 0; ks < KITERS; ks++) {
            // no cp groups on these threads: wait is a no-op, barrier orders data
            __syncthreads();
            const uint32_t sD = smem_base
                + (uint32_t)(ks & (NSTAGE - 1)) * STAGE_BYTES + A_BYTES;
            const uint32_t sB = sD + D_BYTES;
#pragma unroll
            for (int ch = 0; ch < 8; ch++) {
                uint32_t bv[4][4];
#pragma unroll
                for (int b = 0; b < 4; b++) {
                    const int col = cbase + 8 * b;
                    lds128(bv[b], sB + (uint32_t)col * BK
                                 + ((uint32_t)(ch ^ (col & 7)) << 4));
                }
#pragma unroll
                for (int a = 0; a < 8; a++) {
                    const int r = rloc + 4 * a;
                    uint32_t av[4];
                    lds128(av, sD + (uint32_t)r * BK
                              + ((uint32_t)(ch ^ (r & 7)) << 4));
#pragma unroll
                    for (int b = 0; b < 4; b++) {
                        iacc[a][b] = __dp4a((int)av[0], (int)bv[b][0], iacc[a][b]);
                        iacc[a][b] = __dp4a((int)av[1], (int)bv[b][1], iacc[a][b]);
                        iacc[a][b] = __dp4a((int)av[2], (int)bv[b][2], iacc[a][b]);
                        iacc[a][b] = __dp4a((int)av[3], (int)bv[b][3], iacc[a][b]);
                    }
                }
            }
            if (ks & 1) {
                const int g = ks >> 1;
#pragma unroll
                for (int b = 0; b < 4; b++) {
                    float sb = s_sm[g * BN + cbase + 8 * b];
#pragma unroll
                    for (int a = 0; a < 8; a++) {
                        facc[a][b] = fmaf(
                            __int_as_float(iacc[a][b] + MAGIC_I) - MAGICF, sb, facc[a][b]);
                        iacc[a][b] = 0;
                    }
                }
            }
        }

        // epilogue (dp4a half)
#pragma unroll
        for (int a = 0; a < 8; a++) {
            const int m = BMH + rloc + 4 * a;
            float Qv[NG];
#pragma unroll
            for (int g = 0; g < NG; g++) Qv[g] = Q_sm[m * NG + g];
            const float sl = srow_sm[m], zl = zp_sm[m];
            float* orow = out + (size_t)(m0 + m) * ODIM + n0;
#pragma unroll
            for (int b = 0; b < 4; b++) {
                const int ne = cbase + 8 * b;
                float d = 0.f;
#pragma unroll
                for (int g = 0; g < NG; g++)
                    d = fmaf(Qv[g], sz_sm[g * BN + ne], d);
                orow[ne] = fmaf(sl, facc[a][b] - d - zl * C_sm[ne], bias_sm[ne]);
            }
        }
    }
}

// ============================================================================
// Host launch
// ============================================================================
extern "C" void kernel_launch(void* const* d_in, const int* in_sizes, int n_in,
                              void* d_out, int out_size)
{
    const float* x    = nullptr;
    const void*  wraw = nullptr;
    const float* bias = nullptr;
    const float* amb[2] = {nullptr, nullptr};
    int na = 0;

    for (int i = 0; i < n_in; i++) {
        const size_t sz = (size_t)in_sizes[i];
        if (sz == X_ELEMS)       x = (const float*)d_in[i];
        else if (sz == W_ELEMS)  wraw = d_in[i];
        else if (sz == B_ELEMS)  bias = (const float*)d_in[i];
        else if (sz == SZ_ELEMS && na < 2) amb[na++] = (const float*)d_in[i];
    }
    if (!x)    x    = (const float*)d_in[0];
    if (!wraw) wraw = d_in[1];
    if (na < 2) { amb[0] = (const float*)d_in[2]; amb[1] = (const float*)d_in[3]; }
    if (!bias) bias = (const float*)d_in[4];

    float* out = (float*)d_out;

    detpick_kernel<<<1, 1>>>((const int*)wraw, amb[0], amb[1]);
    prep_kernel<<<WCONV_BLOCKS + TOK, 256>>>(wraw, x);
    wprep_kernel<<<ODIM, 128>>>(amb[0], amb[1]);

    cudaFuncSetAttribute(gemm_kernel, cudaFuncAttributeMaxDynamicSharedMemorySize,
                         DYN_SMEM);
    dim3 grid(ODIM / BN, TOK / BMT);   // (64, 32)
    gemm_kernel<<<grid, 512, DYN_SMEM>>>(amb[0], amb[1], bias, out);
}